// round 2
// baseline (speedup 1.0000x reference)
#include <cuda_runtime.h>
#include <cstdint>

// ---------------------------------------------------------------------------
// GCN 2-layer: out = gcnconv2( relu( gcnconv1(x) ) )
// gcnconv(x): h = x@W;  out[d] = sum_e norm[e]*h[src[e]]  (+ self loop) + b
// norm[e] = dinv[src]*w[e]*dinv[dst],  dinv = rsqrt(deg at dst incl self-loop)
// ---------------------------------------------------------------------------

#define N_MAX 100000
#define E_MAX 1600000
#define F_DIM 128            // HID == OUT == 128

// Static scratch (no allocations allowed)
__device__ float g_A[(size_t)N_MAX * F_DIM];   // gemm outputs (lin)
__device__ float g_B[(size_t)N_MAX * F_DIM];   // layer-1 aggregate accumulator
__device__ float g_deg[N_MAX];
__device__ float g_dinv[N_MAX];
__device__ int   g_src[E_MAX];
__device__ int   g_dst[E_MAX];
__device__ float g_norm[E_MAX];
__device__ int   g_is64;

// ---------------------------------------------------------------------------
// Detect int64 vs int32 edge_index: if int64 (little endian), every odd 32-bit
// word of the first rows is a zero high-half (indices < 100000). If int32,
// odd words are random src indices (virtually never all zero).
// ---------------------------------------------------------------------------
__global__ void k_detect(const unsigned* __restrict__ w) {
    __shared__ unsigned s;
    if (threadIdx.x == 0) s = 0u;
    __syncthreads();
    unsigned v = 0;
    for (int i = threadIdx.x; i < 4096; i += blockDim.x) v |= w[2 * i + 1];
    if (v) atomicOr(&s, 1u);
    __syncthreads();
    if (threadIdx.x == 0) g_is64 = (s == 0u) ? 1 : 0;
}

__global__ void k_initdeg(int N) {
    int i = blockIdx.x * blockDim.x + threadIdx.x;
    if (i < N) g_deg[i] = 1.0f;   // self-loop weight
}

// Decode indices once (cached as int32) + degree accumulation at dst.
__global__ void k_deg(const void* __restrict__ ei, const float* __restrict__ w, int E) {
    int e = blockIdx.x * blockDim.x + threadIdx.x;
    if (e >= E) return;
    int s, d;
    if (g_is64) {
        const long long* p = (const long long*)ei;
        s = (int)p[e];
        d = (int)p[(size_t)E + e];
    } else {
        const int* p = (const int*)ei;
        s = p[e];
        d = p[(size_t)E + e];
    }
    g_src[e] = s;
    g_dst[e] = d;
    atomicAdd(&g_deg[d], w[e]);
}

__global__ void k_dinv(int N) {
    int i = blockIdx.x * blockDim.x + threadIdx.x;
    if (i >= N) return;
    float dg = g_deg[i];
    g_dinv[i] = (dg > 0.0f) ? rsqrtf(dg) : 0.0f;
}

__global__ void k_norm(const float* __restrict__ w, int E) {
    int e = blockIdx.x * blockDim.x + threadIdx.x;
    if (e >= E) return;
    g_norm[e] = g_dinv[g_src[e]] * w[e] * g_dinv[g_dst[e]];
}

// ---------------------------------------------------------------------------
// SGEMM: C[M,128] = act(X[M,K]) @ W[K,128]
// BM=64, BN=128 (full), BK=16; 256 threads; each thread 4x8 outputs.
// RELU template fuses relu onto the A-operand load (layer-2 input).
// ---------------------------------------------------------------------------
template <bool RELU>
__global__ __launch_bounds__(256) void k_sgemm128(
    const float* __restrict__ X, const float* __restrict__ W,
    float* __restrict__ C, int M, int K)
{
    __shared__ float Xs[16][64];
    __shared__ float Ws[16][128];

    const int tid = threadIdx.x;
    const int tr = tid >> 4;        // 0..15 (row group)
    const int tc = tid & 15;        // 0..15 (col group)
    const int rowBase = blockIdx.x * 64;

    // X-tile load mapping: 64 rows x 16 k, one float4 per thread
    const int ldr = tid >> 2;           // 0..63
    const int ldk = (tid & 3) * 4;      // 0,4,8,12
    // W-tile load mapping: 16 k-rows x 128, 8 floats per thread
    const int wrow = tid >> 4;          // 0..15
    const int wcol = (tid & 15) * 8;    // 0..120

    float acc[4][8];
#pragma unroll
    for (int i = 0; i < 4; i++)
#pragma unroll
        for (int j = 0; j < 8; j++) acc[i][j] = 0.0f;

    for (int k0 = 0; k0 < K; k0 += 16) {
        // --- load X tile (transposed to Xs[k][row]) ---
        float4 xv = make_float4(0.f, 0.f, 0.f, 0.f);
        int gr = rowBase + ldr;
        if (gr < M) xv = *(const float4*)(X + (size_t)gr * K + k0 + ldk);
        if (RELU) {
            xv.x = fmaxf(xv.x, 0.f); xv.y = fmaxf(xv.y, 0.f);
            xv.z = fmaxf(xv.z, 0.f); xv.w = fmaxf(xv.w, 0.f);
        }
        Xs[ldk + 0][ldr] = xv.x;
        Xs[ldk + 1][ldr] = xv.y;
        Xs[ldk + 2][ldr] = xv.z;
        Xs[ldk + 3][ldr] = xv.w;

        // --- load W tile ---
        float4 w0 = *(const float4*)(W + (size_t)(k0 + wrow) * 128 + wcol);
        float4 w1 = *(const float4*)(W + (size_t)(k0 + wrow) * 128 + wcol + 4);
        *(float4*)&Ws[wrow][wcol]     = w0;
        *(float4*)&Ws[wrow][wcol + 4] = w1;

        __syncthreads();

#pragma unroll
        for (int kk = 0; kk < 16; kk++) {
            float a[4], b[8];
            *(float4*)a       = *(const float4*)&Xs[kk][tr * 4];
            *(float4*)b       = *(const float4*)&Ws[kk][tc * 8];
            *(float4*)(b + 4) = *(const float4*)&Ws[kk][tc * 8 + 4];
#pragma unroll
            for (int i = 0; i < 4; i++)
#pragma unroll
                for (int j = 0; j < 8; j++)
                    acc[i][j] = fmaf(a[i], b[j], acc[i][j]);
        }
        __syncthreads();
    }

#pragma unroll
    for (int i = 0; i < 4; i++) {
        int r = rowBase + tr * 4 + i;
        if (r < M) {
            float4 o0 = make_float4(acc[i][0], acc[i][1], acc[i][2], acc[i][3]);
            float4 o1 = make_float4(acc[i][4], acc[i][5], acc[i][6], acc[i][7]);
            *(float4*)(C + (size_t)r * 128 + tc * 8)     = o0;
            *(float4*)(C + (size_t)r * 128 + tc * 8 + 4) = o1;
        }
    }
}

// ---------------------------------------------------------------------------
// Self-loop + bias init: out[i,:] = dinv[i]^2 * lin[i,:] + bias[:]
// One thread per float4.
// ---------------------------------------------------------------------------
__global__ void k_init_out(const float* __restrict__ lin,
                           const float* __restrict__ bias,
                           float* __restrict__ out, int N)
{
    int idx = blockIdx.x * blockDim.x + threadIdx.x;   // N*32 float4s
    if (idx >= N * 32) return;
    int i = idx >> 5;
    int lane = idx & 31;
    float di = g_dinv[i];
    float s = di * di;
    float4 v = ((const float4*)lin)[idx];
    float4 bb = ((const float4*)bias)[lane];
    float4 o = make_float4(fmaf(v.x, s, bb.x), fmaf(v.y, s, bb.y),
                           fmaf(v.z, s, bb.z), fmaf(v.w, s, bb.w));
    ((float4*)out)[idx] = o;
}

// ---------------------------------------------------------------------------
// Edge scatter: one warp per edge; lane l handles float4 slice l of the row.
// out[dst] += norm * lin[src] via red.global.add.v4.f32 (sm_90+).
// ---------------------------------------------------------------------------
__global__ __launch_bounds__(256) void k_scatter(
    const float* __restrict__ lin, float* __restrict__ out, int E)
{
    int gt = blockIdx.x * blockDim.x + threadIdx.x;
    int e = gt >> 5;
    if (e >= E) return;
    int lane = gt & 31;
    int s = g_src[e];
    int d = g_dst[e];
    float nv = g_norm[e];
    float4 v = ((const float4*)lin)[(size_t)s * 32 + lane];
    v.x *= nv; v.y *= nv; v.z *= nv; v.w *= nv;
    float* addr = out + (size_t)d * 128 + lane * 4;
    asm volatile("red.global.add.v4.f32 [%0], {%1, %2, %3, %4};"
                 :: "l"(addr), "f"(v.x), "f"(v.y), "f"(v.z), "f"(v.w)
                 : "memory");
}

// ---------------------------------------------------------------------------

static inline int cdiv(long long a, long long b) { return (int)((a + b - 1) / b); }

extern "C" void kernel_launch(void* const* d_in, const int* in_sizes, int n_in,
                              void* d_out, int out_size)
{
    const float* x   = (const float*)d_in[0];
    const void*  ei  = d_in[1];                 // int32 or int64, detected on device
    const float* ew  = (const float*)d_in[2];
    const float* W1  = (const float*)d_in[3];
    const float* b1  = (const float*)d_in[4];
    const float* W2  = (const float*)d_in[5];
    const float* b2  = (const float*)d_in[6];
    float* out = (float*)d_out;

    const int HID = in_sizes[4];                 // 128
    const int K1  = in_sizes[3] / HID;           // 256
    const int N   = in_sizes[0] / K1;            // 100000
    const int E   = in_sizes[2];                 // 1600000

    float* A; float* B;
    cudaGetSymbolAddress((void**)&A, g_A);
    cudaGetSymbolAddress((void**)&B, g_B);

    const int T = 256;

    // --- graph normalization ---
    k_detect<<<1, T>>>((const unsigned*)ei);
    k_initdeg<<<cdiv(N, T), T>>>(N);
    k_deg<<<cdiv(E, T), T>>>(ei, ew, E);
    k_dinv<<<cdiv(N, T), T>>>(N);
    k_norm<<<cdiv(E, T), T>>>(ew, E);

    // --- layer 1: A = x @ W1 ; B = dinv^2*A + b1 ; B += scatter(norm * A[src]) ---
    k_sgemm128<false><<<cdiv(N, 64), T>>>(x, W1, A, N, K1);
    k_init_out<<<cdiv((long long)N * 32, T), T>>>(A, b1, B, N);
    k_scatter<<<cdiv((long long)E * 32, T), T>>>(A, B, E);

    // --- layer 2: A = relu(B) @ W2 ; out = dinv^2*A + b2 ; out += scatter ---
    k_sgemm128<true><<<cdiv(N, 64), T>>>(B, W2, A, N, HID);
    k_init_out<<<cdiv((long long)N * 32, T), T>>>(A, b2, out, N);
    k_scatter<<<cdiv((long long)E * 32, T), T>>>(A, out, E);
}